// round 8
// baseline (speedup 1.0000x reference)
#include <cuda_runtime.h>
#include <cstdint>

#define BB   8
#define SS   128
#define DD   300
#define EE   50
#define DEPC 50
#define RROWS 8
#define NTHR 512

__device__ float g_M [BB * SS * SS];
__device__ float g_Pa[BB * SS * DEPC];
__device__ float g_Pb[BB * SS * DEPC];

using ull = unsigned long long;

__device__ __forceinline__ ull pk2(float x, float y) {
    ull r; asm("mov.b64 %0, {%1,%2};" : "=l"(r) : "f"(x), "f"(y)); return r;
}
__device__ __forceinline__ ull f2fma(ull a, ull b, ull c) {
    ull d; asm("fma.rn.f32x2 %0, %1, %2, %3;" : "=l"(d) : "l"(a), "l"(b), "l"(c)); return d;
}
__device__ __forceinline__ ull f2add(ull a, ull b) {
    ull d; asm("add.rn.f32x2 %0, %1, %2;" : "=l"(d) : "l"(a), "l"(b)); return d;
}
__device__ __forceinline__ void upk2(ull v, float& x, float& y) {
    asm("mov.b64 {%0,%1}, %2;" : "=f"(x), "=f"(y) : "l"(v));
}

// =======================================================================
// Prefetch kernels: warm L2 for W/W1 and X (also steer ncu onto k_compute
// at launch position 4). Touch one float per 32B sector; asm keeps loads.
// =======================================================================
__global__ void k_pref_w(const float* __restrict__ a, const float* __restrict__ b) {
    int i = blockIdx.x * blockDim.x + threadIdx.x;
    float v = 0.f;
    if (i < 11250) v += a[i * 8];           // Ww: 90000 floats
    if (i < 3750)  v += b[i * 8];           // W1w: 30000 floats
    asm volatile("" :: "f"(v));
}
__global__ void k_pref_x(const float* __restrict__ a) {
    int i = blockIdx.x * blockDim.x + threadIdx.x;
    float v = 0.f;
    if (i < 38400) v = a[i * 8];            // x: 307200 floats
    asm volatile("" :: "f"(v));
}

// =======================================================================
// k_reduce: M[b,s,t] = (1/E)(sum_e wps[b,s,t,e] + sum_e sl[b,e,s,t])
// (256,4) -> 64-reg budget so the LDG batches actually stay in flight
// (previous 32-reg cap serialized them).
// =======================================================================
__global__ __launch_bounds__(256, 4) void k_reduce(const float* __restrict__ wps,
                                                   const float* __restrict__ sl) {
    __shared__ float W[128 * EE];
    __shared__ float Srow[128];
    __shared__ float SL[256];
    const int tid = threadIdx.x;
    const int blk = blockIdx.x;            // b*128 + s
    const int b   = blk >> 7;
    const int s   = blk & 127;

    const float4* src = reinterpret_cast<const float4*>(wps) + (size_t)blk * 1600;
    float4* W4 = reinterpret_cast<float4*>(W);
    float4 v[6];
#pragma unroll
    for (int k = 0; k < 6; k++) v[k] = src[tid + 256 * k];
    float4 v6;
    const bool tail = tid < 64;
    if (tail) v6 = src[tid + 1536];

    // sl partial (independent loads; with 64 regs these batch wide)
    float slacc;
    {
        const int tcol = tid & 127, eh = tid >> 7;
        const float* sp = sl + (size_t)b * EE * SS * SS
                             + (size_t)(eh * 25) * SS * SS + s * SS + tcol;
        float p[5] = {0.f, 0.f, 0.f, 0.f, 0.f};
#pragma unroll
        for (int e = 0; e < 25; e++) p[e % 5] += sp[(size_t)e * SS * SS];
        slacc = (p[0] + p[1]) + (p[2] + p[3]) + p[4];
    }

#pragma unroll
    for (int k = 0; k < 6; k++) W4[tid + 256 * k] = v[k];
    if (tail) W4[tid + 1536] = v6;
    SL[tid] = slacc;
    __syncthreads();

    {
        const int row = tid >> 1, eh = tid & 1;
        const float* wr = W + row * EE + eh * 25;
        float s1 = 0.f;
#pragma unroll
        for (int i = 0; i < 25; i++) s1 += wr[i];
        s1 += __shfl_xor_sync(0xffffffffu, s1, 1);
        if (eh == 0) Srow[row] = s1;
    }
    __syncthreads();

    if (tid < 128)
        g_M[blk * 128 + tid] = (Srow[tid] + SL[tid] + SL[tid + 128]) * (1.0f / EE);
}

// =======================================================================
// k_compute — weight staging now SOFTWARE-PIPELINED: chunk-0 LDGs issued
// before phase 1; chunk c+1 (and finally W1) loaded during chunk c compute.
// =======================================================================
#define OFF_MSP   0        // 1024 f : packed M row-pairs [t*4+rp] f2
#define OFF_AX    1024     // 2400 f : Ax f2 [d*4+rp]
#define OFF_NS    3424     // 2400 f : g then node, f2 [j*4+rp]
#define OFF_WS    5824     // 30200 f: staged weight chunk (f2 stride 151)
#define OFF_GH    36024    // 3200 f : publish scratch (400*4 ull)
#define OFF_RED   39224    // 128
#define OFF_MEAN  39352    // 8
#define OFF_INVD  39360    // 8
#define SMEM_FLOATS 39368
#define SMEM_BYTES  (SMEM_FLOATS * 4)

__global__ __launch_bounds__(NTHR, 1) void k_compute(
    const float* __restrict__ x,   const float* __restrict__ Ww,
    const float* __restrict__ Wb,  const float* __restrict__ lna,
    const float* __restrict__ lnb, const float* __restrict__ W1w,
    float* __restrict__ node_out)
{
    extern __shared__ float sm[];
    float*  MsPf  = sm + OFF_MSP;
    float2* MsP   = reinterpret_cast<float2*>(MsPf);
    float2* AxP   = reinterpret_cast<float2*>(sm + OFF_AX);
    float2* NsP   = reinterpret_cast<float2*>(sm + OFF_NS);
    float2* Ws2   = reinterpret_cast<float2*>(sm + OFF_WS);
    ull*    GH    = reinterpret_cast<ull*>(sm + OFF_GH);
    float*  red   = sm + OFF_RED;
    float*  means = sm + OFF_MEAN;
    float*  invd  = sm + OFF_INVD;

    const int tid = threadIdx.x;
    const int b   = blockIdx.x >> 4;
    const int s0  = (blockIdx.x & 15) * RROWS;
    const int seg = tid / 100;           // 0..4 active (tid<500)
    const int oj  = tid - seg * 100;
    const bool stg = (tid < 500);

    // ---- pack this block's 8 M rows ----
    const float* Mb = g_M + (size_t)(b * SS + s0) * SS;
    for (int i = tid; i < RROWS * SS; i += NTHR) {
        int r = i >> 7, t = i & 127;
        MsPf[(t * 4 + (r >> 1)) * 2 + (r & 1)] = Mb[i];
    }
    __syncthreads();

    // ---- issue W chunk-0 loads (in flight through phase 1) ----
    float2 sv[30];
    if (stg) {
        const float2* srcw = reinterpret_cast<const float2*>(Ww);
#pragma unroll
        for (int k = 0; k < 30; k++) sv[k] = srcw[k * 500 + tid];
    }

    // ================= Phase 1: Ax[r][d] = sum_t M[r][t]*X[t][d] ============
    if (tid < DD) {
        const float* xb = x + (size_t)b * SS * DD + tid;
        const ulonglong2* mv = reinterpret_cast<const ulonglong2*>(MsP);
        ull acc[4] = {0, 0, 0, 0};
        for (int t0 = 0; t0 < SS; t0 += 16) {
            float xv[16];
#pragma unroll
            for (int u = 0; u < 16; u++) xv[u] = xb[(size_t)(t0 + u) * DD];
#pragma unroll
            for (int u = 0; u < 16; u++) {
                ull x2 = pk2(xv[u], xv[u]);
                ulonglong2 m0 = mv[(t0 + u) * 2], m1 = mv[(t0 + u) * 2 + 1];
                acc[0] = f2fma(m0.x, x2, acc[0]);
                acc[1] = f2fma(m0.y, x2, acc[1]);
                acc[2] = f2fma(m1.x, x2, acc[2]);
                acc[3] = f2fma(m1.y, x2, acc[3]);
            }
        }
#pragma unroll
        for (int rp = 0; rp < 4; rp++)
            *reinterpret_cast<ull*>(&AxP[tid * 4 + rp]) = acc[rp];
    }
    // STS chunk 0 while phase-1 laggards finish
    if (stg) {
#pragma unroll
        for (int k = 0; k < 30; k++) {
            int idx = k * 500 + tid;
            int row = idx / 150, col = idx - row * 150;
            Ws2[row * 151 + col] = sv[k];
        }
    }
    __syncthreads();    // AxP + Ws2(chunk0) ready

    // ================= Phase 2: g = Ax @ W^T + b, pipelined chunks ==========
    for (int c = 0; c < 3; c++) {
        // issue next-chunk loads (c==2 slot prefetches W1 for phase 4)
        if (stg) {
            const float2* srcw = (c < 2)
                ? reinterpret_cast<const float2*>(Ww) + (size_t)(c + 1) * 15000
                : reinterpret_cast<const float2*>(W1w);
#pragma unroll
            for (int k = 0; k < 30; k++) sv[k] = srcw[k * 500 + tid];
        }

        ull acc[4] = {0, 0, 0, 0};
        if (stg) {
            const float2* wr = Ws2 + oj * 151 + seg * 30;
            const int dbase = seg * 60;
            const ulonglong2* axv = reinterpret_cast<const ulonglong2*>(AxP);
#pragma unroll 6
            for (int i = 0; i < 30; i++) {
                float2 wv = wr[i];
                int d = dbase + 2 * i;
                ulonglong2 p0 = axv[d * 2],     p1 = axv[d * 2 + 1];
                ulonglong2 q0 = axv[d * 2 + 2], q1 = axv[d * 2 + 3];
                ull wx = pk2(wv.x, wv.x);
                acc[0] = f2fma(wx, p0.x, acc[0]);
                acc[1] = f2fma(wx, p0.y, acc[1]);
                acc[2] = f2fma(wx, p1.x, acc[2]);
                acc[3] = f2fma(wx, p1.y, acc[3]);
                ull wy = pk2(wv.y, wv.y);
                acc[0] = f2fma(wy, q0.x, acc[0]);
                acc[1] = f2fma(wy, q0.y, acc[1]);
                acc[2] = f2fma(wy, q1.x, acc[2]);
                acc[3] = f2fma(wy, q1.y, acc[3]);
            }
        }
        if (stg && seg) {
            int base = ((seg - 1) * 100 + oj) * 4;
#pragma unroll
            for (int rp = 0; rp < 4; rp++) GH[base + rp] = acc[rp];
        }
        __syncthreads();    // all Ws2 reads + GH writes done

        // combine (tid<100) runs concurrently with next-chunk STS
        if (tid < 100) {
            int j = c * 100 + tid;
            float bj = Wb[j];
            ull b2 = pk2(bj, bj);
#pragma unroll
            for (int rp = 0; rp < 4; rp++) {
                ull v = acc[rp];
#pragma unroll
                for (int s = 0; s < 4; s++) v = f2add(v, GH[(s * 100 + tid) * 4 + rp]);
                *reinterpret_cast<ull*>(&NsP[j * 4 + rp]) = f2add(v, b2);
            }
        }
        if (stg) {
#pragma unroll
            for (int k = 0; k < 30; k++) {
                int idx = k * 500 + tid;
                int row = idx / 150, col = idx - row * 150;
                Ws2[row * 151 + col] = sv[k];
            }
        }
        __syncthreads();    // NsP(chunk c) + Ws2(next) ready
    }

    // ================= Phase 3: LayerNorm (ddof=1) + relu ===================
    const int lane = tid & 31, warp = tid >> 5;
    float gj[RROWS];
    const bool jown = (tid < DD);
    if (jown) {
        const ulonglong2* nv = reinterpret_cast<const ulonglong2*>(NsP + tid * 4);
        ulonglong2 a = nv[0], bq = nv[1];
        upk2(a.x,  gj[0], gj[1]); upk2(a.y,  gj[2], gj[3]);
        upk2(bq.x, gj[4], gj[5]); upk2(bq.y, gj[6], gj[7]);
    }
    {
        float s[RROWS];
#pragma unroll
        for (int r = 0; r < RROWS; r++) s[r] = jown ? gj[r] : 0.f;
#pragma unroll
        for (int off = 16; off; off >>= 1)
#pragma unroll
            for (int r = 0; r < RROWS; r++) s[r] += __shfl_down_sync(0xffffffffu, s[r], off);
        if (lane == 0)
#pragma unroll
            for (int r = 0; r < RROWS; r++) red[warp * RROWS + r] = s[r];
    }
    __syncthreads();
    if (tid < RROWS) {
        float s = 0.f;
#pragma unroll
        for (int w = 0; w < NTHR / 32; w++) s += red[w * RROWS + tid];
        means[tid] = s * (1.0f / DD);
    }
    __syncthreads();
    {
        float s[RROWS];
#pragma unroll
        for (int r = 0; r < RROWS; r++) {
            float dv = jown ? (gj[r] - means[r]) : 0.f;
            s[r] = dv * dv;
        }
#pragma unroll
        for (int off = 16; off; off >>= 1)
#pragma unroll
            for (int r = 0; r < RROWS; r++) s[r] += __shfl_down_sync(0xffffffffu, s[r], off);
        if (lane == 0)
#pragma unroll
            for (int r = 0; r < RROWS; r++) red[warp * RROWS + r] = s[r];
    }
    __syncthreads();
    if (tid < RROWS) {
        float s = 0.f;
#pragma unroll
        for (int w = 0; w < NTHR / 32; w++) s += red[w * RROWS + tid];
        float stdv = sqrtf(s * (1.0f / (DD - 1)));   // ddof = 1
        invd[tid] = 1.0f / (stdv + 1e-6f);
    }
    __syncthreads();

    if (jown) {
        float a = lna[tid], bb2 = lnb[tid];
        float nv[RROWS];
#pragma unroll
        for (int r = 0; r < RROWS; r++) {
            float v = a * (gj[r] - means[r]) * invd[r] + bb2;
            nv[r] = v > 0.f ? v : 0.f;
            node_out[(size_t)(b * SS + s0 + r) * DD + tid] = nv[r];
        }
#pragma unroll
        for (int rp = 0; rp < 4; rp++)
            NsP[tid * 4 + rp] = make_float2(nv[2 * rp], nv[2 * rp + 1]);
    }
    __syncthreads();

    // ================= Phase 4: pa/pb (W1 already staged in Ws2) ============
    ull acc[4] = {0, 0, 0, 0};
    if (stg) {
        const float2* wr = Ws2 + oj * 151 + seg * 30;    // row oj: e=oj>>1, half=oj&1
        const int dbase = seg * 60;
        const ulonglong2* nsv = reinterpret_cast<const ulonglong2*>(NsP);
#pragma unroll 6
        for (int i = 0; i < 30; i++) {
            float2 wv = wr[i];
            int d = dbase + 2 * i;
            ulonglong2 p0 = nsv[d * 2],     p1 = nsv[d * 2 + 1];
            ulonglong2 q0 = nsv[d * 2 + 2], q1 = nsv[d * 2 + 3];
            ull wx = pk2(wv.x, wv.x);
            acc[0] = f2fma(wx, p0.x, acc[0]);
            acc[1] = f2fma(wx, p0.y, acc[1]);
            acc[2] = f2fma(wx, p1.x, acc[2]);
            acc[3] = f2fma(wx, p1.y, acc[3]);
            ull wy = pk2(wv.y, wv.y);
            acc[0] = f2fma(wy, q0.x, acc[0]);
            acc[1] = f2fma(wy, q0.y, acc[1]);
            acc[2] = f2fma(wy, q1.x, acc[2]);
            acc[3] = f2fma(wy, q1.y, acc[3]);
        }
    }
    if (stg && seg) {
        int base = ((seg - 1) * 100 + oj) * 4;
#pragma unroll
        for (int rp = 0; rp < 4; rp++) GH[base + rp] = acc[rp];
    }
    __syncthreads();
    if (tid < 100) {
        int e = tid >> 1, half = tid & 1;    // W1 row tid = [e][half*D .. ]
        float pv[RROWS];
#pragma unroll
        for (int rp = 0; rp < 4; rp++) {
            ull v = acc[rp];
#pragma unroll
            for (int s = 0; s < 4; s++) v = f2add(v, GH[(s * 100 + tid) * 4 + rp]);
            upk2(v, pv[2 * rp], pv[2 * rp + 1]);
        }
        float* dst = (half == 0 ? g_Pa : g_Pb) + (size_t)(b * SS + s0) * DEPC + e;
#pragma unroll
        for (int r = 0; r < RROWS; r++) dst[r * DEPC] = pv[r];
    }
}

// =======================================================================
// k_edge: edge[b,i,j,e] = pa[b,j,e] + pb[b,i,e] + W1_b[e]
// =======================================================================
__global__ __launch_bounds__(400) void k_edge(const float* __restrict__ W1b,
                                              float* __restrict__ edge) {
    const int bi0 = blockIdx.x * 2;
    const int b   = bi0 >> 7;
    const int tid = threadIdx.x;
    const int e2  = tid % 25;
    const int j0  = tid / 25;

    float2 w = reinterpret_cast<const float2*>(W1b)[e2];
    const ull* pa = reinterpret_cast<const ull*>(g_Pa + (size_t)b * SS * DEPC);
    ull pav[8];
#pragma unroll
    for (int k = 0; k < 8; k++) pav[k] = pa[(j0 + 16 * k) * 25 + e2];

#pragma unroll
    for (int r = 0; r < 2; r++) {
        int bi = bi0 + r;
        float2 pv = reinterpret_cast<const float2*>(g_Pb + (size_t)bi * DEPC)[e2];
        ull pr = pk2(pv.x + w.x, pv.y + w.y);
        ull* out = reinterpret_cast<ull*>(edge + (size_t)bi * SS * DEPC);
#pragma unroll
        for (int k = 0; k < 8; k++) out[(j0 + 16 * k) * 25 + e2] = f2add(pav[k], pr);
    }
}

// =======================================================================
extern "C" void kernel_launch(void* const* d_in, const int* in_sizes, int n_in,
                              void* d_out, int out_size) {
    const float* wps = (const float*)d_in[0];
    /* d_in[1] = weight_adj (int64) — unused */
    const float* x   = (const float*)d_in[2];
    const float* sl  = (const float*)d_in[3];
    const float* Ww  = (const float*)d_in[4];
    const float* Wb  = (const float*)d_in[5];
    const float* lna = (const float*)d_in[6];
    const float* lnb = (const float*)d_in[7];
    const float* W1w = (const float*)d_in[8];
    const float* W1b = (const float*)d_in[9];

    float* out  = (float*)d_out;
    float* node = out;
    float* edge = out + BB * SS * DD;

    cudaFuncSetAttribute((const void*)k_compute,
                         cudaFuncAttributeMaxDynamicSharedMemorySize, SMEM_BYTES);

    k_pref_w <<<44, 256>>>(Ww, W1w);
    k_pref_x <<<150, 256>>>(x);
    k_reduce <<<BB * SS, 256>>>(wps, sl);
    k_compute<<<BB * (SS / RROWS), NTHR, SMEM_BYTES>>>(x, Ww, Wb, lna, lnb, W1w, node);
    k_edge   <<<BB * SS / 2, 400>>>(W1b, edge);
}

// round 11
// speedup vs baseline: 1.0865x; 1.0865x over previous
#include <cuda_runtime.h>
#include <cstdint>

#define BB   8
#define SS   128
#define DD   300
#define EE   50
#define DEPC 50
#define RROWS 8
#define NTHR 512

__device__ float g_M  [BB * SS * SS];
__device__ float g_Wt [DD * DD];        // Wt[d][j]  = Ww[j][d]
__device__ float g_W1t[DD * 100];       // W1t[d][o] = W1w[o>>1][(o&1)*300 + d]
__device__ float g_Pa [BB * SS * DEPC];
__device__ float g_Pb [BB * SS * DEPC];

using ull = unsigned long long;

__device__ __forceinline__ ull pk2(float x, float y) {
    ull r; asm("mov.b64 %0, {%1,%2};" : "=l"(r) : "f"(x), "f"(y)); return r;
}
__device__ __forceinline__ ull f2fma(ull a, ull b, ull c) {
    ull d; asm("fma.rn.f32x2 %0, %1, %2, %3;" : "=l"(d) : "l"(a), "l"(b), "l"(c)); return d;
}
__device__ __forceinline__ ull f2add(ull a, ull b) {
    ull d; asm("add.rn.f32x2 %0, %1, %2;" : "=l"(d) : "l"(a), "l"(b)); return d;
}
__device__ __forceinline__ void upk2(ull v, float& x, float& y) {
    asm("mov.b64 {%0,%1}, %2;" : "=f"(x), "=f"(y) : "l"(v));
}
// 4 accumulators (rp=0..3) updated by one scalar weight wv
__device__ __forceinline__ void fma4(ull* a, float wv, ull r0, ull r1, ull r2, ull r3) {
    ull w = pk2(wv, wv);
    a[0] = f2fma(w, r0, a[0]); a[1] = f2fma(w, r1, a[1]);
    a[2] = f2fma(w, r2, a[2]); a[3] = f2fma(w, r3, a[3]);
}

// =======================================================================
// k_prep: transpose W -> g_Wt, W1 -> g_W1t, prefetch x into L2.
// =======================================================================
__global__ void k_prep(const float* __restrict__ Ww, const float* __restrict__ W1w,
                       const float* __restrict__ x) {
    const int bid = blockIdx.x;
    const int tid = threadIdx.x;
    if (bid < 100) {                       // W 32x32 tile transpose
        __shared__ float tile[32][33];
        const int jt = (bid / 10) * 32, dt = (bid % 10) * 32;
        const int tx = tid & 31, ty = tid >> 5;
#pragma unroll
        for (int yy = ty; yy < 32; yy += 8) {
            int j = jt + yy, d = dt + tx;
            tile[yy][tx] = (j < DD && d < DD) ? Ww[j * DD + d] : 0.f;
        }
        __syncthreads();
#pragma unroll
        for (int yy = ty; yy < 32; yy += 8) {
            int d = dt + yy, j = jt + tx;
            if (d < DD && j < DD) g_Wt[d * DD + j] = tile[tx][yy];
        }
    } else if (bid < 120) {                // W1t scatter (30000 elements)
        for (int idx = (bid - 100) * 256 + tid; idx < 100 * DD; idx += 20 * 256) {
            int e = idx / 600, c = idx - e * 600;
            int d = c % DD, half = c / DD;
            g_W1t[d * 100 + 2 * e + half] = W1w[idx];
        }
    } else {                               // x L2 prefetch (1 float / 32B sector)
        int i = (bid - 120) * 256 + tid;
        float v = 0.f;
        if (i < 38400) v = x[i * 8];
        asm volatile("" :: "f"(v));
    }
}

// =======================================================================
// k_reduce: M[b,s,t] = (1/E)(sum_e wps[b,s,t,e] + sum_e sl[b,e,s,t])
// 2 s-rows per block; smem is DYNAMIC (52.2 KB > 48 KB static cap).
// =======================================================================
#define RED_SMEM_FLOATS (2 * 128 * EE + 256)     // W (12800) + SL (256)
#define RED_SMEM_BYTES  (RED_SMEM_FLOATS * 4)    // 52224 B

__global__ __launch_bounds__(256, 3) void k_reduce(const float* __restrict__ wps,
                                                   const float* __restrict__ sl) {
    extern __shared__ float rsm[];
    float* W  = rsm;                       // 12800 f
    float* SL = rsm + 2 * 128 * EE;        // 256 f
    const int tid = threadIdx.x;
    const int blk = blockIdx.x;            // 512: b = blk>>6, s0 = (blk&63)*2
    const int b   = blk >> 6;
    const int s0  = (blk & 63) * 2;

    const float4* src = reinterpret_cast<const float4*>(wps) + (size_t)(b * SS + s0) * 1600;
    float4* W4 = reinterpret_cast<float4*>(W);
    float4 v[12];
#pragma unroll
    for (int k = 0; k < 12; k++) v[k] = src[tid + 256 * k];
    float4 v12;
    const bool tail = tid < 128;
    if (tail) v12 = src[tid + 3072];

    // sl: thread = (sp = tid>>7, t = tid&127), 50 strided loads
    float slacc;
    {
        const float* sp_ = sl + (size_t)b * EE * SS * SS + (s0 + (tid >> 7)) * SS + (tid & 127);
        float p[5] = {0.f, 0.f, 0.f, 0.f, 0.f};
#pragma unroll
        for (int e = 0; e < EE; e++) p[e % 5] += sp_[(size_t)e * SS * SS];
        slacc = (p[0] + p[1]) + (p[2] + p[3]) + p[4];
    }

#pragma unroll
    for (int k = 0; k < 12; k++) W4[tid + 256 * k] = v[k];
    if (tail) W4[tid + 3072] = v12;
    SL[tid] = slacc;
    __syncthreads();

    // rowsum: thread owns one of 256 (sp,t) rows of 50 floats
    float s1 = 0.f;
    const float* wr = W + tid * EE;
#pragma unroll
    for (int i = 0; i < EE; i++) s1 += wr[i];
    g_M[(size_t)(b * SS + s0 + (tid >> 7)) * SS + (tid & 127)] = (s1 + SL[tid]) * (1.0f / EE);
}

// =======================================================================
// k_compute: per (b, 8-row group). All weight reads are coalesced LDG.128
// from the transposed copies; smem crossbar only carries Ms/AxP/NsP/GH.
// =======================================================================
#define OFF_MS    0        // 1024 f : Ms[r*128+t]
#define OFF_AX    1024     // 2400 f : AxP f2 [d*4+rp]
#define OFF_NS    3424     // 2400 f : g/node f2 [j*4+rp]
#define OFF_GH    5824     // 12000 f: 6000 ull combine scratch
#define OFF_RED   17824    // 128
#define OFF_MEAN  17952    // 8
#define OFF_INVD  17960    // 8
#define SMEM_FLOATS 17968
#define SMEM_BYTES  (SMEM_FLOATS * 4)

__global__ __launch_bounds__(NTHR, 1) void k_compute(
    const float* __restrict__ x,   const float* __restrict__ Wb,
    const float* __restrict__ lna, const float* __restrict__ lnb,
    float* __restrict__ node_out)
{
    extern __shared__ float sm[];
    float*  Ms    = sm + OFF_MS;
    float2* AxP   = reinterpret_cast<float2*>(sm + OFF_AX);
    float2* NsP   = reinterpret_cast<float2*>(sm + OFF_NS);
    ull*    GH    = reinterpret_cast<ull*>(sm + OFF_GH);
    float*  red   = sm + OFF_RED;
    float*  means = sm + OFF_MEAN;
    float*  invd  = sm + OFF_INVD;

    const int tid = threadIdx.x;
    const int b   = blockIdx.x >> 4;
    const int s0  = (blockIdx.x & 15) * RROWS;

    // ---- stage M rows plain [r][t] ----
    if (tid < 256)
        reinterpret_cast<float4*>(Ms)[tid] =
            reinterpret_cast<const float4*>(g_M + (size_t)(b * SS + s0) * SS)[tid];
    __syncthreads();

    // ========== Phase 1: Ax[r][d] = sum_t M[r][t] x[t][d] ==========
    // thread = (tseg<4 over t, dq<75 over d-quads); acc1[r*2+dp] packs (d,d+1)
    ull acc1[16];
    if (tid < 300) {
        const int tseg = tid / 75, dq = tid % 75, d0 = dq * 4;
        const float* xb = x + (size_t)b * SS * DD + d0;
        const int t0 = tseg * 32;
#pragma unroll
        for (int k = 0; k < 16; k++) acc1[k] = 0;
#pragma unroll 1
        for (int tb = 0; tb < 4; tb++) {
            float4 xq[8];
#pragma unroll
            for (int u = 0; u < 8; u++)
                xq[u] = *reinterpret_cast<const float4*>(xb + (size_t)(t0 + tb * 8 + u) * DD);
#pragma unroll
            for (int u = 0; u < 8; u++) {
                const int t = t0 + tb * 8 + u;
                ull xlo = pk2(xq[u].x, xq[u].y), xhi = pk2(xq[u].z, xq[u].w);
#pragma unroll
                for (int r = 0; r < 8; r++) {
                    ull mm = pk2(Ms[r * SS + t], Ms[r * SS + t]);
                    acc1[r * 2]     = f2fma(mm, xlo, acc1[r * 2]);
                    acc1[r * 2 + 1] = f2fma(mm, xhi, acc1[r * 2 + 1]);
                }
            }
        }
        if (tseg) {
            ull* g = GH + (size_t)((tseg - 1) * 75 + dq) * 16;
#pragma unroll
            for (int k = 0; k < 16; k++) g[k] = acc1[k];
        }
    }
    __syncthreads();
    if (tid < 75) {
#pragma unroll
        for (int s = 0; s < 3; s++)
#pragma unroll
            for (int k = 0; k < 16; k++) acc1[k] = f2add(acc1[k], GH[(size_t)(s * 75 + tid) * 16 + k]);
        float v[8][4];
#pragma unroll
        for (int r = 0; r < 8; r++) {
            upk2(acc1[r * 2],     v[r][0], v[r][1]);
            upk2(acc1[r * 2 + 1], v[r][2], v[r][3]);
        }
        const int d0 = tid * 4;
#pragma unroll
        for (int dd = 0; dd < 4; dd++)
#pragma unroll
            for (int rp = 0; rp < 4; rp++)
                AxP[(d0 + dd) * 4 + rp] = make_float2(v[2 * rp][dd], v[2 * rp + 1][dd]);
    }
    __syncthreads();

    // ========== Phase 2: g = Ax @ W^T + b ==========
    // thread = (seg<6 over 50-d ranges, jg<75 over j-quads); W via LDG from g_Wt
    ull acc2[16];
#pragma unroll
    for (int k = 0; k < 16; k++) acc2[k] = 0;
    if (tid < 450) {
        const int seg = tid / 75, jg = tid % 75;
        const int d0 = seg * 50, j0 = jg * 4;
        const float* wtb = g_Wt + j0;
#pragma unroll 1
        for (int pb = 0; pb < 5; pb++) {
            float4 wq[10];
#pragma unroll
            for (int u = 0; u < 5; u++) {
                int d = d0 + (pb * 5 + u) * 2;
                wq[2 * u]     = *reinterpret_cast<const float4*>(wtb + (size_t)d * DD);
                wq[2 * u + 1] = *reinterpret_cast<const float4*>(wtb + (size_t)(d + 1) * DD);
            }
#pragma unroll
            for (int u = 0; u < 5; u++) {
                int d = d0 + (pb * 5 + u) * 2;
                const ulonglong2* ap = reinterpret_cast<const ulonglong2*>(&AxP[d * 4]);
                ulonglong2 a0 = ap[0], a1 = ap[1], b0 = ap[2], b1 = ap[3];
                float4 wa = wq[2 * u], wv = wq[2 * u + 1];
                fma4(acc2 + 0,  wa.x, a0.x, a0.y, a1.x, a1.y);
                fma4(acc2 + 4,  wa.y, a0.x, a0.y, a1.x, a1.y);
                fma4(acc2 + 8,  wa.z, a0.x, a0.y, a1.x, a1.y);
                fma4(acc2 + 12, wa.w, a0.x, a0.y, a1.x, a1.y);
                fma4(acc2 + 0,  wv.x, b0.x, b0.y, b1.x, b1.y);
                fma4(acc2 + 4,  wv.y, b0.x, b0.y, b1.x, b1.y);
                fma4(acc2 + 8,  wv.z, b0.x, b0.y, b1.x, b1.y);
                fma4(acc2 + 12, wv.w, b0.x, b0.y, b1.x, b1.y);
            }
        }
        if (seg) {
            ull* g = GH + (size_t)((seg - 1) * 75 + jg) * 16;
#pragma unroll
            for (int k = 0; k < 16; k++) g[k] = acc2[k];
        }
    }
    __syncthreads();
    if (tid < 75) {
#pragma unroll
        for (int s = 0; s < 5; s++)
#pragma unroll
            for (int k = 0; k < 16; k++) acc2[k] = f2add(acc2[k], GH[(size_t)(s * 75 + tid) * 16 + k]);
#pragma unroll
        for (int jj = 0; jj < 4; jj++) {
            int j = tid * 4 + jj;
            ull b2 = pk2(Wb[j], Wb[j]);
#pragma unroll
            for (int rp = 0; rp < 4; rp++) {
                ull vv = f2add(acc2[jj * 4 + rp], b2);
                *reinterpret_cast<ull*>(&NsP[j * 4 + rp]) = vv;
            }
        }
    }
    __syncthreads();

    // ========== Phase 3: LayerNorm (ddof=1) + relu ==========
    const int lane = tid & 31, warp = tid >> 5;
    float gj[RROWS];
    const bool jown = (tid < DD);
    if (jown) {
        const ulonglong2* nv = reinterpret_cast<const ulonglong2*>(NsP + tid * 4);
        ulonglong2 a = nv[0], bq = nv[1];
        upk2(a.x,  gj[0], gj[1]); upk2(a.y,  gj[2], gj[3]);
        upk2(bq.x, gj[4], gj[5]); upk2(bq.y, gj[6], gj[7]);
    }
    {
        float s[RROWS];
#pragma unroll
        for (int r = 0; r < RROWS; r++) s[r] = jown ? gj[r] : 0.f;
#pragma unroll
        for (int off = 16; off; off >>= 1)
#pragma unroll
            for (int r = 0; r < RROWS; r++) s[r] += __shfl_down_sync(0xffffffffu, s[r], off);
        if (lane == 0)
#pragma unroll
            for (int r = 0; r < RROWS; r++) red[warp * RROWS + r] = s[r];
    }
    __syncthreads();
    if (tid < RROWS) {
        float s = 0.f;
#pragma unroll
        for (int w = 0; w < NTHR / 32; w++) s += red[w * RROWS + tid];
        means[tid] = s * (1.0f / DD);
    }
    __syncthreads();
    {
        float s[RROWS];
#pragma unroll
        for (int r = 0; r < RROWS; r++) {
            float dv = jown ? (gj[r] - means[r]) : 0.f;
            s[r] = dv * dv;
        }
#pragma unroll
        for (int off = 16; off; off >>= 1)
#pragma unroll
            for (int r = 0; r < RROWS; r++) s[r] += __shfl_down_sync(0xffffffffu, s[r], off);
        if (lane == 0)
#pragma unroll
            for (int r = 0; r < RROWS; r++) red[warp * RROWS + r] = s[r];
    }
    __syncthreads();
    if (tid < RROWS) {
        float s = 0.f;
#pragma unroll
        for (int w = 0; w < NTHR / 32; w++) s += red[w * RROWS + tid];
        float stdv = sqrtf(s * (1.0f / (DD - 1)));   // ddof = 1
        invd[tid] = 1.0f / (stdv + 1e-6f);
    }
    __syncthreads();

    if (jown) {
        float a = lna[tid], bb2 = lnb[tid];
        float nv[RROWS];
#pragma unroll
        for (int r = 0; r < RROWS; r++) {
            float v = a * (gj[r] - means[r]) * invd[r] + bb2;
            nv[r] = v > 0.f ? v : 0.f;
            node_out[(size_t)(b * SS + s0 + r) * DD + tid] = nv[r];
        }
#pragma unroll
        for (int rp = 0; rp < 4; rp++)
            NsP[tid * 4 + rp] = make_float2(nv[2 * rp], nv[2 * rp + 1]);
    }
    __syncthreads();

    // ========== Phase 4: P = node @ W1^T (o<100 interleaved pa/pb) ==========
    ull acc4[16];
#pragma unroll
    for (int k = 0; k < 16; k++) acc4[k] = 0;
    if (tid < 250) {
        const int seg = tid / 25, og = tid % 25;
        const int d0 = seg * 30, o0 = og * 4;
        const float* wtb = g_W1t + o0;
#pragma unroll 1
        for (int pb = 0; pb < 3; pb++) {
            float4 wq[10];
#pragma unroll
            for (int u = 0; u < 5; u++) {
                int d = d0 + (pb * 5 + u) * 2;
                wq[2 * u]     = *reinterpret_cast<const float4*>(wtb + (size_t)d * 100);
                wq[2 * u + 1] = *reinterpret_cast<const float4*>(wtb + (size_t)(d + 1) * 100);
            }
#pragma unroll
            for (int u = 0; u < 5; u++) {
                int d = d0 + (pb * 5 + u) * 2;
                const ulonglong2* np = reinterpret_cast<const ulonglong2*>(&NsP[d * 4]);
                ulonglong2 a0 = np[0], a1 = np[1], b0 = np[2], b1 = np[3];
                float4 wa = wq[2 * u], wv = wq[2 * u + 1];
                fma4(acc4 + 0,  wa.x, a0.x, a0.y, a1.x, a1.y);
                fma4(acc4 + 4,  wa.y, a0.x, a0.y, a1.x, a1.y);
                fma4(acc4 + 8,  wa.z, a0.x, a0.y, a1.x, a1.y);
                fma4(acc4 + 12, wa.w, a0.x, a0.y, a1.x, a1.y);
                fma4(acc4 + 0,  wv.x, b0.x, b0.y, b1.x, b1.y);
                fma4(acc4 + 4,  wv.y, b0.x, b0.y, b1.x, b1.y);
                fma4(acc4 + 8,  wv.z, b0.x, b0.y, b1.x, b1.y);
                fma4(acc4 + 12, wv.w, b0.x, b0.y, b1.x, b1.y);
            }
        }
        if (seg) {
            ull* g = GH + (size_t)((seg - 1) * 25 + og) * 16;
#pragma unroll
            for (int k = 0; k < 16; k++) g[k] = acc4[k];
        }
    }
    __syncthreads();
    if (tid < 25) {
#pragma unroll
        for (int s = 0; s < 9; s++)
#pragma unroll
            for (int k = 0; k < 16; k++) acc4[k] = f2add(acc4[k], GH[(size_t)(s * 25 + tid) * 16 + k]);
#pragma unroll
        for (int jj = 0; jj < 4; jj++) {
            int o = tid * 4 + jj, e = o >> 1;
            float* dst = ((o & 1) ? g_Pb : g_Pa) + (size_t)(b * SS + s0) * DEPC + e;
#pragma unroll
            for (int rp = 0; rp < 4; rp++) {
                float f0, f1;
                upk2(acc4[jj * 4 + rp], f0, f1);
                dst[(2 * rp) * DEPC]     = f0;
                dst[(2 * rp + 1) * DEPC] = f1;
            }
        }
    }
}

// =======================================================================
// k_edge: edge[b,i,j,e] = pa[b,j,e] + pb[b,i,e] + W1_b[e]
// =======================================================================
__global__ __launch_bounds__(400) void k_edge(const float* __restrict__ W1b,
                                              float* __restrict__ edge) {
    const int bi0 = blockIdx.x * 2;
    const int b   = bi0 >> 7;
    const int tid = threadIdx.x;
    const int e2  = tid % 25;
    const int j0  = tid / 25;

    float2 w = reinterpret_cast<const float2*>(W1b)[e2];
    const ull* pa = reinterpret_cast<const ull*>(g_Pa + (size_t)b * SS * DEPC);
    ull pav[8];
#pragma unroll
    for (int k = 0; k < 8; k++) pav[k] = pa[(j0 + 16 * k) * 25 + e2];

#pragma unroll
    for (int r = 0; r < 2; r++) {
        int bi = bi0 + r;
        float2 pv = reinterpret_cast<const float2*>(g_Pb + (size_t)bi * DEPC)[e2];
        ull pr = pk2(pv.x + w.x, pv.y + w.y);
        ull* out = reinterpret_cast<ull*>(edge + (size_t)bi * SS * DEPC);
#pragma unroll
        for (int k = 0; k < 8; k++) out[(j0 + 16 * k) * 25 + e2] = f2add(pav[k], pr);
    }
}

// =======================================================================
extern "C" void kernel_launch(void* const* d_in, const int* in_sizes, int n_in,
                              void* d_out, int out_size) {
    const float* wps = (const float*)d_in[0];
    /* d_in[1] = weight_adj (int64) — unused */
    const float* x   = (const float*)d_in[2];
    const float* sl  = (const float*)d_in[3];
    const float* Ww  = (const float*)d_in[4];
    const float* Wb  = (const float*)d_in[5];
    const float* lna = (const float*)d_in[6];
    const float* lnb = (const float*)d_in[7];
    const float* W1w = (const float*)d_in[8];
    const float* W1b = (const float*)d_in[9];

    float* out  = (float*)d_out;
    float* node = out;
    float* edge = out + BB * SS * DD;

    cudaFuncSetAttribute((const void*)k_reduce,
                         cudaFuncAttributeMaxDynamicSharedMemorySize, RED_SMEM_BYTES);
    cudaFuncSetAttribute((const void*)k_compute,
                         cudaFuncAttributeMaxDynamicSharedMemorySize, SMEM_BYTES);

    k_prep   <<<270, 256>>>(Ww, W1w, x);
    k_reduce <<<BB * SS / 2, 256, RED_SMEM_BYTES>>>(wps, sl);
    k_compute<<<BB * (SS / RROWS), NTHR, SMEM_BYTES>>>(x, Wb, lna, lnb, node);
    k_edge   <<<BB * SS / 2, 400>>>(W1b, edge);
}